// round 14
// baseline (speedup 1.0000x reference)
#include <cuda_runtime.h>
#include <cuda_bf16.h>
#include <math.h>
#include <math_constants.h>
#include <stdint.h>

// ---------------------------------------------------------------------------
// Problem constants
// ---------------------------------------------------------------------------
#define B        2
#define NQ       2048
#define NCTX     512
#define F        1024
#define MID      1024
#define NHEAD    16
#define HDIM     64
#define ROWS_X   (B * NQ)      // 4096
#define ROWS_C   (B * NCTX)    // 1024

// exp((s+b)*0.125) = 2^(s*CC + b*CC) ; bias table is pre-multiplied by CC
#define CC 0.18033688011112042f   // 0.125 * log2(e)

// ---------------------------------------------------------------------------
// Scratch (device globals)
// ---------------------------------------------------------------------------
__device__ __nv_bfloat16 g_xh  [ROWS_X * F];
__device__ __nv_bfloat16 g_ch  [ROWS_C * F];
__device__ __nv_bfloat16 g_qkv [ROWS_X * 3 * MID];    // self merged [q|k|v]
__device__ __nv_bfloat16 g_qc  [ROWS_X * MID];
__device__ __nv_bfloat16 g_kvc [ROWS_C * 2 * MID];
__device__ __nv_bfloat16 g_ao  [ROWS_X * MID];
__device__ float         g_x1  [ROWS_X * F];
__device__ float         g_tbl [2 * NHEAD * 4096];    // pre-scaled by CC
__device__ float         g_bvec[6144];
__device__ float         g_bpart[8 * 6144];
__device__ __nv_bfloat16 g_wqkv [3 * MID * F];
__device__ __nv_bfloat16 g_wto  [F * MID];
__device__ __nv_bfloat16 g_wtq2 [MID * F];
__device__ __nv_bfloat16 g_wtkv2[2 * MID * F];
__device__ __nv_bfloat16 g_wto2 [F * MID];

// ---------------------------------------------------------------------------
// PTX helpers
// ---------------------------------------------------------------------------
__device__ __forceinline__ uint32_t su32(const void* p) {
    return (uint32_t)__cvta_generic_to_shared(p);
}
__device__ __forceinline__ void cp16(uint32_t dst, const void* src) {
    asm volatile("cp.async.cg.shared.global [%0], [%1], 16;" :: "r"(dst), "l"(src));
}
__device__ __forceinline__ void cp_commit() {
    asm volatile("cp.async.commit_group;");
}
template<int N> __device__ __forceinline__ void cp_wait() {
    asm volatile("cp.async.wait_group %0;" :: "n"(N));
}
__device__ __forceinline__ void ldm_x4(uint32_t r[4], uint32_t addr) {
    asm volatile("ldmatrix.sync.aligned.m8n8.x4.shared.b16 {%0,%1,%2,%3}, [%4];"
                 : "=r"(r[0]), "=r"(r[1]), "=r"(r[2]), "=r"(r[3]) : "r"(addr));
}
__device__ __forceinline__ void ldm_x4_t(uint32_t r[4], uint32_t addr) {
    asm volatile("ldmatrix.sync.aligned.m8n8.x4.trans.shared.b16 {%0,%1,%2,%3}, [%4];"
                 : "=r"(r[0]), "=r"(r[1]), "=r"(r[2]), "=r"(r[3]) : "r"(addr));
}
__device__ __forceinline__ void mma_bf16(float c[4], const uint32_t a[4], const uint32_t b[2]) {
    asm volatile(
        "mma.sync.aligned.m16n8k16.row.col.f32.bf16.bf16.f32 "
        "{%0,%1,%2,%3}, {%4,%5,%6,%7}, {%8,%9}, {%0,%1,%2,%3};\n"
        : "+f"(c[0]), "+f"(c[1]), "+f"(c[2]), "+f"(c[3])
        : "r"(a[0]), "r"(a[1]), "r"(a[2]), "r"(a[3]), "r"(b[0]), "r"(b[1]));
}
__device__ __forceinline__ uint32_t packbf(float lo, float hi) {
    __nv_bfloat162 t = __floats2bfloat162_rn(lo, hi);
    return *reinterpret_cast<uint32_t*>(&t);
}
__device__ __forceinline__ float exp2a(float x) {
    float y;
    asm("ex2.approx.ftz.f32 %0, %1;" : "=f"(y) : "f"(x));
    return y;
}

// ---------------------------------------------------------------------------
// LN-hat, warp-per-row: x -> (x-mean)*rsqrt(var+eps) bf16. Single pass.
// ---------------------------------------------------------------------------
__global__ __launch_bounds__(256) void lnw_kernel(
    const float* __restrict__ x, __nv_bfloat16* __restrict__ out)
{
    const int row  = (blockIdx.x * 256 + threadIdx.x) >> 5;
    const int lane = threadIdx.x & 31;

    const float4* xr = (const float4*)(x + (size_t)row * F);
    float4 v[8];
    #pragma unroll
    for (int i = 0; i < 8; i++) v[i] = xr[lane + 32 * i];

    float s = 0.f, s2 = 0.f;
    #pragma unroll
    for (int i = 0; i < 8; i++) {
        s  += v[i].x + v[i].y + v[i].z + v[i].w;
        s2 += v[i].x * v[i].x + v[i].y * v[i].y + v[i].z * v[i].z + v[i].w * v[i].w;
    }
    #pragma unroll
    for (int o = 16; o > 0; o >>= 1) {
        s  += __shfl_xor_sync(0xffffffffu, s,  o);
        s2 += __shfl_xor_sync(0xffffffffu, s2, o);
    }
    const float mean = s * (1.0f / F);
    const float var  = s2 * (1.0f / F) - mean * mean;
    const float rs   = rsqrtf(var + 1e-5f);

    __nv_bfloat16* orow = out + (size_t)row * F;
    #pragma unroll
    for (int i = 0; i < 8; i++) {
        __nv_bfloat162 p0 = __floats2bfloat162_rn((v[i].x - mean) * rs, (v[i].y - mean) * rs);
        __nv_bfloat162 p1 = __floats2bfloat162_rn((v[i].z - mean) * rs, (v[i].w - mean) * rs);
        uint2 u = make_uint2(*(uint32_t*)&p0, *(uint32_t*)&p1);
        *(uint2*)(orow + (lane + 32 * i) * 4) = u;
    }
}

// ---------------------------------------------------------------------------
// Both rel-pos bias tables in one launch (pre-multiplied by CC)
// ---------------------------------------------------------------------------
__global__ __launch_bounds__(256) void bias2_kernel(
    const float* __restrict__ e0, const float* __restrict__ e1,
    float* __restrict__ tbl)
{
    const int idx = blockIdx.x * 256 + threadIdx.x;
    const float* emb = (idx < 65536) ? e0 : e1;
    const int li = idx & 65535;
    const int h = li >> 12;
    const int p = li & 4095;
    const int rel = p - 2048;
    const int retv = (rel >= 0) ? 16 : 0;
    const int na = (rel < 0) ? -rel : rel;
    int bucket;
    if (na < 8) {
        bucket = retv + na;
    } else {
        float t = logf((float)na * 0.125f) / 2.7725887f;   // log(16)
        int vl = 8 + (int)(t * 8.0f);
        bucket = retv + min(vl, 15);
    }
    tbl[idx] = emb[bucket * NHEAD + h] * CC;
}

// ---------------------------------------------------------------------------
// All 6 weight transposes (with optional gamma fold) in one segmented launch.
// ---------------------------------------------------------------------------
struct WDesc {
    const float* W[6];
    const float* G[6];
    __nv_bfloat16* Wt[6];
    int K[6], N[6];
    int start[7];
};

__global__ __launch_bounds__(256) void wtrans_all_kernel(WDesc d)
{
    __shared__ float t[32][33];
    const int bid = blockIdx.x;
    int s = 0;
    #pragma unroll
    for (int i = 1; i < 6; i++) if (bid >= d.start[i]) s = i;

    const float* W = d.W[s];
    const float* G = d.G[s];
    __nv_bfloat16* Wt = d.Wt[s];
    const int K = d.K[s], N = d.N[s];
    const int bi = bid - d.start[s];
    const int nbx = N >> 5;
    const int n0 = (bi % nbx) * 32;
    const int k0 = (bi / nbx) * 32;

    const int tx = threadIdx.x, ty = threadIdx.y;
    #pragma unroll
    for (int i = 0; i < 4; i++)
        t[ty + 8 * i][tx] = W[(size_t)(k0 + ty + 8 * i) * N + n0 + tx];
    __syncthreads();
    const float gv = G ? G[k0 + tx] : 1.0f;
    #pragma unroll
    for (int i = 0; i < 4; i++)
        Wt[(size_t)(n0 + ty + 8 * i) * K + k0 + tx] = __float2bfloat16(t[tx][ty + 8 * i] * gv);
}

// ---------------------------------------------------------------------------
// Bias rows: bvec[n] = sum_k beta[k]*W[k][n]. Split-k (8 chunks) + reduce.
// ---------------------------------------------------------------------------
struct BDesc {
    const float* b[4];
    const float* W[4];
    int N[4];
    int startblk[5];
};

__global__ __launch_bounds__(256) void bvec_part_kernel(BDesc d, float* __restrict__ part)
{
    const int cb = blockIdx.x;
    const int kc = blockIdx.y;
    int s = 0;
    #pragma unroll
    for (int i = 1; i < 4; i++) if (cb >= d.startblk[i]) s = i;
    const float* bet = d.b[s];
    const float* W = d.W[s];
    const int N = d.N[s];
    const int col = (cb - d.startblk[s]) * 256 + threadIdx.x;

    float acc = 0.f;
    const int k0 = kc * 128;
    #pragma unroll 8
    for (int k = k0; k < k0 + 128; k++)
        acc += bet[k] * W[(size_t)k * N + col];
    part[kc * 6144 + cb * 256 + threadIdx.x] = acc;
}

__global__ __launch_bounds__(256) void bvec_sum_kernel(
    const float* __restrict__ part, float* __restrict__ out)
{
    const int i = blockIdx.x * 256 + threadIdx.x;
    float a = 0.f;
    #pragma unroll
    for (int j = 0; j < 8; j++) a += part[j * 6144 + i];
    out[i] = a;
}

// ---------------------------------------------------------------------------
// bf16 GEMM: C[M,N] = A[M,K] @ Bt[N,K]^T (+bias[N]) (+res, fp32 path only)
// 128x128 tile, Ktile 32, 8 warps, 3-stage cp.async ring, ldmatrix frags.
// ---------------------------------------------------------------------------
#define GSTAGE_ELEM (128 * 40)
#define GEMM_SMEM   (3 * 2 * GSTAGE_ELEM * 2)   // 61440 bytes

template<bool OBF>
__global__ __launch_bounds__(256) void gemm_bf16(
    const __nv_bfloat16* __restrict__ A, const __nv_bfloat16* __restrict__ Bt,
    void* __restrict__ Cv, int M, int N, int K,
    const float* __restrict__ bias, const float* __restrict__ res)
{
    extern __shared__ __nv_bfloat16 dsm[];
    __nv_bfloat16* As = dsm;
    __nv_bfloat16* Bs = dsm + 3 * GSTAGE_ELEM;

    const int tid = threadIdx.x;
    const int warp = tid >> 5, lane = tid & 31;
    const int q = lane >> 2, cq = lane & 3;
    const int wm = (warp >> 2) * 64, wn = (warp & 3) * 32;
    const int bm = blockIdx.y * 128, bn = blockIdx.x * 128;

    float acc[4][4][4];
    #pragma unroll
    for (int mt = 0; mt < 4; mt++)
        #pragma unroll
        for (int nt = 0; nt < 4; nt++)
            #pragma unroll
            for (int e = 0; e < 4; e++) acc[mt][nt][e] = 0.f;

    const int lr = tid >> 2;
    const int lc = (tid & 3) * 8;

    auto load_tile = [&](int kt, int st) {
        const __nv_bfloat16* Ag = A + (size_t)bm * K + kt * 32 + lc;
        const __nv_bfloat16* Bg = Bt + (size_t)bn * K + kt * 32 + lc;
        __nv_bfloat16* as = As + st * GSTAGE_ELEM;
        __nv_bfloat16* bs = Bs + st * GSTAGE_ELEM;
        cp16(su32(as + lr * 40 + lc),        Ag + (size_t)lr * K);
        cp16(su32(as + (lr + 64) * 40 + lc), Ag + (size_t)(lr + 64) * K);
        cp16(su32(bs + lr * 40 + lc),        Bg + (size_t)lr * K);
        cp16(su32(bs + (lr + 64) * 40 + lc), Bg + (size_t)(lr + 64) * K);
    };

    const int KT = K / 32;
    load_tile(0, 0); cp_commit();
    load_tile(1, 1); cp_commit();

    for (int kt = 0; kt < KT; kt++) {
        if (kt + 2 < KT) { load_tile(kt + 2, (kt + 2) % 3); cp_commit(); cp_wait<2>(); }
        else if (kt + 1 < KT) cp_wait<1>();
        else cp_wait<0>();
        __syncthreads();

        const __nv_bfloat16* as = As + (kt % 3) * GSTAGE_ELEM;
        const __nv_bfloat16* bs = Bs + (kt % 3) * GSTAGE_ELEM;
        #pragma unroll
        for (int ks = 0; ks < 2; ks++) {
            uint32_t af[4][4], bfr[2][4];
            #pragma unroll
            for (int mt = 0; mt < 4; mt++) {
                const int row = wm + mt * 16 + ((lane >> 3) & 1) * 8 + (lane & 7);
                const int col = ks * 16 + (lane >> 4) * 8;
                ldm_x4(af[mt], su32(as + row * 40 + col));
            }
            #pragma unroll
            for (int pn = 0; pn < 2; pn++) {
                const int row = wn + pn * 16 + (lane >> 4) * 8 + (lane & 7);
                const int col = ks * 16 + ((lane >> 3) & 1) * 8;
                ldm_x4(bfr[pn], su32(bs + row * 40 + col));
            }
            #pragma unroll
            for (int mt = 0; mt < 4; mt++)
                #pragma unroll
                for (int nt = 0; nt < 4; nt++)
                    mma_bf16(acc[mt][nt], af[mt], &bfr[nt >> 1][(nt & 1) * 2]);
        }
        __syncthreads();
    }

    #pragma unroll
    for (int mt = 0; mt < 4; mt++) {
        #pragma unroll
        for (int nt = 0; nt < 4; nt++) {
            const int c0 = bn + wn + nt * 8 + 2 * cq;
            #pragma unroll
            for (int half = 0; half < 2; half++) {
                const int row = bm + wm + mt * 16 + q + half * 8;
                float v0 = acc[mt][nt][half * 2 + 0];
                float v1 = acc[mt][nt][half * 2 + 1];
                if (bias) { v0 += bias[c0]; v1 += bias[c0 + 1]; }
                const size_t base = (size_t)row * N + c0;
                if (OBF) {
                    __nv_bfloat16* C = (__nv_bfloat16*)Cv;
                    *(uint32_t*)(C + base) = packbf(v0, v1);
                } else {
                    float* C = (float*)Cv;
                    if (res) { v0 += res[base]; v1 += res[base + 1]; }
                    *(float2*)(C + base) = make_float2(v0, v1);
                }
            }
        }
    }
}

// ---------------------------------------------------------------------------
// Flash attention, bf16 MMA, max-free exp2 softmax.
// R14: 4 warps x 32 q-rows each (128 thr/CTA, same 128-row Q tile). Each K/V
// fragment now feeds 4 MMAs (2 m-tiles x 2 halves) instead of 2 -> ldmatrix
// traffic per CTA per chunk halves; the SMEM crossbar was the binding pipe.
// Fused per-kt: K-frags -> QK MMAs (both m-tiles) -> exp -> V-frags -> PV.
// ---------------------------------------------------------------------------
template<int QSTR, int KVSTR>
__global__ __launch_bounds__(128, 3) void attn_bf16(
    const __nv_bfloat16* __restrict__ qb, const __nv_bfloat16* __restrict__ kvb,
    __nv_bfloat16* __restrict__ ob, const float* __restrict__ tbl,
    int n, int m, int mnoff)
{
    __shared__ __nv_bfloat16 Ks[2][64 * 72];
    __shared__ __nv_bfloat16 Vs[2][64 * 72];
    __shared__ float sb[2][192];

    const int tid = threadIdx.x;
    const int warp = tid >> 5, lane = tid & 31;
    const int q = lane >> 2, cq = lane & 3;
    const int b = blockIdx.z, h = blockIdx.y;
    const int q0 = blockIdx.x * 128;
    const int rb = warp * 32;            // this warp's 32-row q slab
    const float* tblh = tbl + h * 4096;

    // Q fragments for both m-tiles
    uint32_t qf[2][4][4];
    #pragma unroll
    for (int mt = 0; mt < 2; mt++) {
        const int r0 = rb + mt * 16 + q;
        const __nv_bfloat16* qr0 = qb + (size_t)(b * n + q0 + r0) * QSTR + h * HDIM;
        const __nv_bfloat16* qr1 = qr0 + 8 * (size_t)QSTR;
        #pragma unroll
        for (int ks = 0; ks < 4; ks++) {
            qf[mt][ks][0] = *(const uint32_t*)(qr0 + ks * 16 + cq * 2);
            qf[mt][ks][1] = *(const uint32_t*)(qr1 + ks * 16 + cq * 2);
            qf[mt][ks][2] = *(const uint32_t*)(qr0 + ks * 16 + cq * 2 + 8);
            qf[mt][ks][3] = *(const uint32_t*)(qr1 + ks * 16 + cq * 2 + 8);
        }
    }

    float o[2][8][4];
    #pragma unroll
    for (int mt = 0; mt < 2; mt++)
        #pragma unroll
        for (int dt = 0; dt < 8; dt++)
            #pragma unroll
            for (int e = 0; e < 4; e++) o[mt][dt][e] = 0.f;
    float lp[2][2] = {{0.f, 0.f}, {0.f, 0.f}};   // per-lane partial row sums

    const __nv_bfloat16* kvbase = kvb + (size_t)(b * m) * KVSTR + h * HDIM;
    const int lr0 = tid >> 3;            // 0..15
    const int lc8 = (tid & 7) * 8;

    auto load_kv = [&](int c, int bi) {
        const __nv_bfloat16* kg = kvbase + (size_t)(c * 64) * KVSTR;
        #pragma unroll
        for (int i = 0; i < 4; i++) {
            const int r = lr0 + i * 16;
            cp16(su32(&Ks[bi][r * 72 + lc8]), kg + (size_t)r * KVSTR + lc8);
            cp16(su32(&Vs[bi][r * 72 + lc8]), kg + MID + (size_t)r * KVSTR + lc8);
        }
    };

    const int C = m / 64;
    const int sbase = 2048 - q0 - mnoff - 127;
    load_kv(0, 0); cp_commit();
    for (int t = tid; t < 191; t += 128) sb[0][t] = tblh[sbase + t];

    for (int c = 0; c < C; c++) {
        cp_wait<0>();
        __syncthreads();   // chunk c data + sb[c&1] visible; all past chunk c-1 reads

        if (c + 1 < C) {
            load_kv(c + 1, (c + 1) & 1);
            cp_commit();
            for (int t = tid; t < 191; t += 128)
                sb[(c + 1) & 1][t] = tblh[sbase + (c + 1) * 64 + t];
        }

        const __nv_bfloat16* ks_b = Ks[c & 1];
        const __nv_bfloat16* vs_b = Vs[c & 1];
        const float* sbc = sb[c & 1];

        // ---- per-kt (16 j columns): K-frags -> QK (both mt) -> exp -> PV ----
        #pragma unroll
        for (int kt = 0; kt < 4; kt++) {
            // K fragments for this 16-j block, shared by both m-tiles
            uint32_t kf[4][4];
            #pragma unroll
            for (int ks = 0; ks < 4; ks++) {
                const int row = kt * 16 + (lane >> 4) * 8 + (lane & 7);
                const int col = ks * 16 + ((lane >> 3) & 1) * 8;
                ldm_x4(kf[ks], su32(ks_b + row * 72 + col));
            }

            uint32_t ap[2][4];
            #pragma unroll
            for (int mt = 0; mt < 2; mt++) {
                float s2[2][4];
                #pragma unroll
                for (int half = 0; half < 2; half++)
                    #pragma unroll
                    for (int e = 0; e < 4; e++) s2[half][e] = 0.f;

                #pragma unroll
                for (int ks = 0; ks < 4; ks++) {
                    mma_bf16(s2[0], qf[mt][ks], &kf[ks][0]);
                    mma_bf16(s2[1], qf[mt][ks], &kf[ks][2]);
                }

                const int r0l = rb + mt * 16 + q;
                const int r1l = r0l + 8;
                #pragma unroll
                for (int half = 0; half < 2; half++) {
                    #pragma unroll
                    for (int e = 0; e < 2; e++) {
                        const int jl = (2 * kt + half) * 8 + 2 * cq + e;
                        const float p0 = exp2a(fmaf(s2[half][e],     CC, sbc[jl - r0l + 127]));
                        const float p1 = exp2a(fmaf(s2[half][2 + e], CC, sbc[jl - r1l + 127]));
                        s2[half][e]     = p0;
                        s2[half][2 + e] = p1;
                        lp[mt][0] += p0;
                        lp[mt][1] += p1;
                    }
                }
                ap[mt][0] = packbf(s2[0][0], s2[0][1]);
                ap[mt][1] = packbf(s2[0][2], s2[0][3]);
                ap[mt][2] = packbf(s2[1][0], s2[1][1]);
                ap[mt][3] = packbf(s2[1][2], s2[1][3]);
            }

            // V fragments, each used by 4 MMAs (2 m-tiles x 2 o-halves)
            #pragma unroll
            for (int dp = 0; dp < 4; dp++) {
                uint32_t bv[4];
                const int row = kt * 16 + ((lane >> 3) & 1) * 8 + (lane & 7);
                const int col = dp * 16 + (lane >> 4) * 8;
                ldm_x4_t(bv, su32(vs_b + row * 72 + col));
                #pragma unroll
                for (int mt = 0; mt < 2; mt++) {
                    mma_bf16(o[mt][2 * dp],     ap[mt], &bv[0]);
                    mma_bf16(o[mt][2 * dp + 1], ap[mt], &bv[2]);
                }
            }
        }
        // next iteration's barrier orders buffer reuse
    }

    // deferred row-sum reduction over the 4 cq lanes + store
    #pragma unroll
    for (int mt = 0; mt < 2; mt++) {
        float l0 = lp[mt][0], l1 = lp[mt][1];
        l0 += __shfl_xor_sync(0xffffffffu, l0, 1);
        l0 += __shfl_xor_sync(0xffffffffu, l0, 2);
        l1 += __shfl_xor_sync(0xffffffffu, l1, 1);
        l1 += __shfl_xor_sync(0xffffffffu, l1, 2);
        const float inv0 = 1.0f / l0;
        const float inv1 = 1.0f / l1;
        const int r0l = rb + mt * 16 + q;
        __nv_bfloat16* or0 = ob + (size_t)(b * n + q0 + r0l) * MID + h * HDIM;
        __nv_bfloat16* or1 = or0 + 8 * (size_t)MID;
        #pragma unroll
        for (int dt = 0; dt < 8; dt++) {
            const int cc2 = dt * 8 + 2 * cq;
            *(uint32_t*)(or0 + cc2) = packbf(o[mt][dt][0] * inv0, o[mt][dt][1] * inv0);
            *(uint32_t*)(or1 + cc2) = packbf(o[mt][dt][2] * inv1, o[mt][dt][3] * inv1);
        }
    }
}

// ---------------------------------------------------------------------------
// Launch
// ---------------------------------------------------------------------------
extern "C" void kernel_launch(void* const* d_in, const int* in_sizes, int n_in,
                              void* d_out, int out_size)
{
    (void)in_sizes; (void)n_in; (void)out_size;

    const float* x       = (const float*)d_in[0];
    const float* ctx     = (const float*)d_in[1];
    const float* sa_ng   = (const float*)d_in[2];
    const float* sa_nb   = (const float*)d_in[3];
    const float* sa_ncg  = (const float*)d_in[4];
    const float* sa_ncb  = (const float*)d_in[5];
    const float* sa_wq   = (const float*)d_in[6];
    const float* sa_wkv  = (const float*)d_in[7];
    const float* sa_wo   = (const float*)d_in[8];
    const float* sa_bo   = (const float*)d_in[9];
    const float* sa_rel  = (const float*)d_in[10];
    const float* ca_ng   = (const float*)d_in[11];
    const float* ca_nb   = (const float*)d_in[12];
    const float* ca_ncg  = (const float*)d_in[13];
    const float* ca_ncb  = (const float*)d_in[14];
    const float* ca_wq   = (const float*)d_in[15];
    const float* ca_wkv  = (const float*)d_in[16];
    const float* ca_wo   = (const float*)d_in[17];
    const float* ca_bo   = (const float*)d_in[18];
    const float* ca_rel  = (const float*)d_in[19];
    float* out = (float*)d_out;

    __nv_bfloat16 *xh, *ch, *qkv, *qc, *kvc, *ao, *wqkv, *wto, *wtq2, *wtkv2, *wto2;
    float *x1, *tbl, *bvec, *bpart;
    cudaGetSymbolAddress((void**)&xh,    g_xh);
    cudaGetSymbolAddress((void**)&ch,    g_ch);
    cudaGetSymbolAddress((void**)&qkv,   g_qkv);
    cudaGetSymbolAddress((void**)&qc,    g_qc);
    cudaGetSymbolAddress((void**)&kvc,   g_kvc);
    cudaGetSymbolAddress((void**)&ao,    g_ao);
    cudaGetSymbolAddress((void**)&x1,    g_x1);
    cudaGetSymbolAddress((void**)&tbl,   g_tbl);
    cudaGetSymbolAddress((void**)&bvec,  g_bvec);
    cudaGetSymbolAddress((void**)&bpart, g_bpart);
    cudaGetSymbolAddress((void**)&wqkv,  g_wqkv);
    cudaGetSymbolAddress((void**)&wto,   g_wto);
    cudaGetSymbolAddress((void**)&wtq2,  g_wtq2);
    cudaGetSymbolAddress((void**)&wtkv2, g_wtkv2);
    cudaGetSymbolAddress((void**)&wto2,  g_wto2);

    cudaFuncSetAttribute(gemm_bf16<true>,  cudaFuncAttributeMaxDynamicSharedMemorySize, GEMM_SMEM);
    cudaFuncSetAttribute(gemm_bf16<false>, cudaFuncAttributeMaxDynamicSharedMemorySize, GEMM_SMEM);

    // ---- prep: folded weight transposes, bias rows (split-k), rel tables ----
    WDesc wd;
    wd.W[0] = sa_wq;  wd.G[0] = sa_ng;  wd.Wt[0] = wqkv;            wd.K[0] = F;   wd.N[0] = MID;
    wd.W[1] = sa_wkv; wd.G[1] = sa_ncg; wd.Wt[1] = wqkv + MID * F;  wd.K[1] = F;   wd.N[1] = 2 * MID;
    wd.W[2] = sa_wo;  wd.G[2] = nullptr;wd.Wt[2] = wto;             wd.K[2] = MID; wd.N[2] = F;
    wd.W[3] = ca_wq;  wd.G[3] = ca_ng;  wd.Wt[3] = wtq2;            wd.K[3] = F;   wd.N[3] = MID;
    wd.W[4] = ca_wkv; wd.G[4] = ca_ncg; wd.Wt[4] = wtkv2;           wd.K[4] = F;   wd.N[4] = 2 * MID;
    wd.W[5] = ca_wo;  wd.G[5] = nullptr;wd.Wt[5] = wto2;            wd.K[5] = MID; wd.N[5] = F;
    int cum = 0;
    for (int i = 0; i < 6; i++) {
        wd.start[i] = cum;
        cum += (wd.N[i] / 32) * (wd.K[i] / 32);
    }
    wd.start[6] = cum;
    wtrans_all_kernel<<<cum, dim3(32, 8)>>>(wd);

    BDesc bd;
    bd.b[0] = sa_nb;  bd.W[0] = sa_wq;  bd.N[0] = MID;
    bd.b[1] = sa_ncb; bd.W[1] = sa_wkv; bd.N[1] = 2 * MID;
    bd.b[2] = ca_nb;  bd.W[2] = ca_wq;  bd.N[2] = MID;
    bd.b[3] = ca_ncb; bd.W[3] = ca_wkv; bd.N[3] = 2 * MID;
    int bcum = 0;
    for (int i = 0; i < 4; i++) { bd.startblk[i] = bcum; bcum += bd.N[i] / 256; }
    bd.startblk[4] = bcum;
    bvec_part_kernel<<<dim3(bcum, 8), 256>>>(bd, bpart);
    bvec_sum_kernel<<<bcum, 256>>>(bpart, bvec);

    bias2_kernel<<<512, 256>>>(sa_rel, ca_rel, tbl);

    // ---------------- self-attention ----------------
    lnw_kernel<<<ROWS_X / 8, 256>>>(x, xh);
    gemm_bf16<true ><<<dim3(3 * MID / 128, ROWS_X / 128), 256, GEMM_SMEM>>>(
        xh, wqkv, qkv, ROWS_X, 3 * MID, F, bvec, nullptr);
    attn_bf16<3 * MID, 3 * MID><<<dim3(NQ / 128, NHEAD, B), 128>>>(
        qkv, qkv + MID, ao, tbl, NQ, NQ, 0);
    gemm_bf16<false><<<dim3(F / 128, ROWS_X / 128), 256, GEMM_SMEM>>>(
        ao, wto, x1, ROWS_X, F, MID, sa_bo, x);

    // ---------------- cross-attention ----------------
    lnw_kernel<<<ROWS_X / 8, 256>>>(x1, xh);
    lnw_kernel<<<ROWS_C / 8, 256>>>(ctx, ch);
    gemm_bf16<true ><<<dim3(MID / 128, ROWS_X / 128), 256, GEMM_SMEM>>>(
        xh, wtq2, qc, ROWS_X, MID, F, bvec + 3 * MID, nullptr);
    gemm_bf16<true ><<<dim3(2 * MID / 128, ROWS_C / 128), 256, GEMM_SMEM>>>(
        ch, wtkv2, kvc, ROWS_C, 2 * MID, F, bvec + 4 * MID, nullptr);
    attn_bf16<MID, 2 * MID><<<dim3(NQ / 128, NHEAD, B), 128>>>(
        qc, kvc, ao, tbl + NHEAD * 4096, NQ, NCTX, NCTX - NQ);
    gemm_bf16<false><<<dim3(F / 128, ROWS_X / 128), 256, GEMM_SMEM>>>(
        ao, wto2, out, ROWS_X, F, MID, ca_bo, x1);
}

// round 15
// speedup vs baseline: 1.5494x; 1.5494x over previous
#include <cuda_runtime.h>
#include <cuda_bf16.h>
#include <math.h>
#include <math_constants.h>
#include <stdint.h>

// ---------------------------------------------------------------------------
// Problem constants
// ---------------------------------------------------------------------------
#define B        2
#define NQ       2048
#define NCTX     512
#define F        1024
#define MID      1024
#define NHEAD    16
#define HDIM     64
#define ROWS_X   (B * NQ)      // 4096
#define ROWS_C   (B * NCTX)    // 1024

// exp((s+b)*0.125) = 2^(s*CC + b*CC) ; bias table is pre-multiplied by CC
#define CC 0.18033688011112042f   // 0.125 * log2(e)

// ---------------------------------------------------------------------------
// Scratch (device globals)
// ---------------------------------------------------------------------------
__device__ __nv_bfloat16 g_xh  [ROWS_X * F];
__device__ __nv_bfloat16 g_ch  [ROWS_C * F];
__device__ __nv_bfloat16 g_qkv [ROWS_X * 3 * MID];    // self merged [q|k|v]
__device__ __nv_bfloat16 g_qc  [ROWS_X * MID];
__device__ __nv_bfloat16 g_kvc [ROWS_C * 2 * MID];
__device__ __nv_bfloat16 g_ao  [ROWS_X * MID];
__device__ float         g_x1  [ROWS_X * F];
__device__ float         g_tbl [2 * NHEAD * 4096];    // pre-scaled by CC
__device__ float         g_bvec[6144];
__device__ float         g_bpart[8 * 6144];
__device__ __nv_bfloat16 g_wqkv [3 * MID * F];
__device__ __nv_bfloat16 g_wto  [F * MID];
__device__ __nv_bfloat16 g_wtq2 [MID * F];
__device__ __nv_bfloat16 g_wtkv2[2 * MID * F];
__device__ __nv_bfloat16 g_wto2 [F * MID];

// ---------------------------------------------------------------------------
// PTX helpers
// ---------------------------------------------------------------------------
__device__ __forceinline__ uint32_t su32(const void* p) {
    return (uint32_t)__cvta_generic_to_shared(p);
}
__device__ __forceinline__ void cp16(uint32_t dst, const void* src) {
    asm volatile("cp.async.cg.shared.global [%0], [%1], 16;" :: "r"(dst), "l"(src));
}
__device__ __forceinline__ void cp_commit() {
    asm volatile("cp.async.commit_group;");
}
template<int N> __device__ __forceinline__ void cp_wait() {
    asm volatile("cp.async.wait_group %0;" :: "n"(N));
}
__device__ __forceinline__ void ldm_x4(uint32_t r[4], uint32_t addr) {
    asm volatile("ldmatrix.sync.aligned.m8n8.x4.shared.b16 {%0,%1,%2,%3}, [%4];"
                 : "=r"(r[0]), "=r"(r[1]), "=r"(r[2]), "=r"(r[3]) : "r"(addr));
}
__device__ __forceinline__ void ldm_x4_t(uint32_t r[4], uint32_t addr) {
    asm volatile("ldmatrix.sync.aligned.m8n8.x4.trans.shared.b16 {%0,%1,%2,%3}, [%4];"
                 : "=r"(r[0]), "=r"(r[1]), "=r"(r[2]), "=r"(r[3]) : "r"(addr));
}
__device__ __forceinline__ void mma_bf16(float c[4], const uint32_t a[4], const uint32_t b[2]) {
    asm volatile(
        "mma.sync.aligned.m16n8k16.row.col.f32.bf16.bf16.f32 "
        "{%0,%1,%2,%3}, {%4,%5,%6,%7}, {%8,%9}, {%0,%1,%2,%3};\n"
        : "+f"(c[0]), "+f"(c[1]), "+f"(c[2]), "+f"(c[3])
        : "r"(a[0]), "r"(a[1]), "r"(a[2]), "r"(a[3]), "r"(b[0]), "r"(b[1]));
}
__device__ __forceinline__ uint32_t packbf(float lo, float hi) {
    __nv_bfloat162 t = __floats2bfloat162_rn(lo, hi);
    return *reinterpret_cast<uint32_t*>(&t);
}
__device__ __forceinline__ float exp2a(float x) {
    float y;
    asm("ex2.approx.ftz.f32 %0, %1;" : "=f"(y) : "f"(x));
    return y;
}

// ---------------------------------------------------------------------------
// LN-hat, warp-per-row: x -> (x-mean)*rsqrt(var+eps) bf16. Single pass.
// ---------------------------------------------------------------------------
__device__ __forceinline__ void lnw_row(
    const float* __restrict__ x, __nv_bfloat16* __restrict__ out,
    int row, int lane)
{
    const float4* xr = (const float4*)(x + (size_t)row * F);
    float4 v[8];
    #pragma unroll
    for (int i = 0; i < 8; i++) v[i] = xr[lane + 32 * i];

    float s = 0.f, s2 = 0.f;
    #pragma unroll
    for (int i = 0; i < 8; i++) {
        s  += v[i].x + v[i].y + v[i].z + v[i].w;
        s2 += v[i].x * v[i].x + v[i].y * v[i].y + v[i].z * v[i].z + v[i].w * v[i].w;
    }
    #pragma unroll
    for (int o = 16; o > 0; o >>= 1) {
        s  += __shfl_xor_sync(0xffffffffu, s,  o);
        s2 += __shfl_xor_sync(0xffffffffu, s2, o);
    }
    const float mean = s * (1.0f / F);
    const float var  = s2 * (1.0f / F) - mean * mean;
    const float rs   = rsqrtf(var + 1e-5f);

    __nv_bfloat16* orow = out + (size_t)row * F;
    #pragma unroll
    for (int i = 0; i < 8; i++) {
        __nv_bfloat162 p0 = __floats2bfloat162_rn((v[i].x - mean) * rs, (v[i].y - mean) * rs);
        __nv_bfloat162 p1 = __floats2bfloat162_rn((v[i].z - mean) * rs, (v[i].w - mean) * rs);
        uint2 u = make_uint2(*(uint32_t*)&p0, *(uint32_t*)&p1);
        *(uint2*)(orow + (lane + 32 * i) * 4) = u;
    }
}

__global__ __launch_bounds__(256) void lnw_kernel(
    const float* __restrict__ x, __nv_bfloat16* __restrict__ out)
{
    const int row  = (blockIdx.x * 256 + threadIdx.x) >> 5;
    lnw_row(x, out, row, threadIdx.x & 31);
}

// merged cross-pass LN: blocks [0, nb1) process x1->xh, rest process ctx->ch
__global__ __launch_bounds__(256) void lnw2_kernel(
    const float* __restrict__ x1, __nv_bfloat16* __restrict__ o1, int nb1,
    const float* __restrict__ x2, __nv_bfloat16* __restrict__ o2)
{
    const int lane = threadIdx.x & 31;
    if (blockIdx.x < (unsigned)nb1) {
        const int row = (blockIdx.x * 256 + threadIdx.x) >> 5;
        lnw_row(x1, o1, row, lane);
    } else {
        const int row = (((blockIdx.x - nb1) * 256) + threadIdx.x) >> 5;
        lnw_row(x2, o2, row, lane);
    }
}

// ---------------------------------------------------------------------------
// Prep fused tail: rel-pos tables (blocks 0..511) + bvec reduce (blocks 512+)
// ---------------------------------------------------------------------------
__global__ __launch_bounds__(256) void bias2_sum_kernel(
    const float* __restrict__ e0, const float* __restrict__ e1,
    float* __restrict__ tbl,
    const float* __restrict__ part, float* __restrict__ bout, int nb_sum)
{
    if (blockIdx.x < 512) {
        const int idx = blockIdx.x * 256 + threadIdx.x;
        const float* emb = (idx < 65536) ? e0 : e1;
        const int li = idx & 65535;
        const int h = li >> 12;
        const int p = li & 4095;
        const int rel = p - 2048;
        const int retv = (rel >= 0) ? 16 : 0;
        const int na = (rel < 0) ? -rel : rel;
        int bucket;
        if (na < 8) {
            bucket = retv + na;
        } else {
            float t = logf((float)na * 0.125f) / 2.7725887f;   // log(16)
            int vl = 8 + (int)(t * 8.0f);
            bucket = retv + min(vl, 15);
        }
        tbl[idx] = emb[bucket * NHEAD + h] * CC;
    } else {
        const int bi = blockIdx.x - 512;
        if (bi < nb_sum) {
            const int i = bi * 256 + threadIdx.x;
            float a = 0.f;
            #pragma unroll
            for (int j = 0; j < 8; j++) a += part[j * 6144 + i];
            bout[i] = a;
        }
    }
}

// ---------------------------------------------------------------------------
// All 6 weight transposes (with optional gamma fold) in one segmented launch.
// ---------------------------------------------------------------------------
struct WDesc {
    const float* W[6];
    const float* G[6];
    __nv_bfloat16* Wt[6];
    int K[6], N[6];
    int start[7];
};

__global__ __launch_bounds__(256) void wtrans_all_kernel(WDesc d)
{
    __shared__ float t[32][33];
    const int bid = blockIdx.x;
    int s = 0;
    #pragma unroll
    for (int i = 1; i < 6; i++) if (bid >= d.start[i]) s = i;

    const float* W = d.W[s];
    const float* G = d.G[s];
    __nv_bfloat16* Wt = d.Wt[s];
    const int K = d.K[s], N = d.N[s];
    const int bi = bid - d.start[s];
    const int nbx = N >> 5;
    const int n0 = (bi % nbx) * 32;
    const int k0 = (bi / nbx) * 32;

    const int tx = threadIdx.x, ty = threadIdx.y;
    #pragma unroll
    for (int i = 0; i < 4; i++)
        t[ty + 8 * i][tx] = W[(size_t)(k0 + ty + 8 * i) * N + n0 + tx];
    __syncthreads();
    const float gv = G ? G[k0 + tx] : 1.0f;
    #pragma unroll
    for (int i = 0; i < 4; i++)
        Wt[(size_t)(n0 + ty + 8 * i) * K + k0 + tx] = __float2bfloat16(t[tx][ty + 8 * i] * gv);
}

// ---------------------------------------------------------------------------
// Bias rows split-k partials: part[kc][n] = sum_{k in chunk} beta[k]*W[k][n]
// ---------------------------------------------------------------------------
struct BDesc {
    const float* b[4];
    const float* W[4];
    int N[4];
    int startblk[5];
};

__global__ __launch_bounds__(256) void bvec_part_kernel(BDesc d, float* __restrict__ part)
{
    const int cb = blockIdx.x;
    const int kc = blockIdx.y;
    int s = 0;
    #pragma unroll
    for (int i = 1; i < 4; i++) if (cb >= d.startblk[i]) s = i;
    const float* bet = d.b[s];
    const float* W = d.W[s];
    const int N = d.N[s];
    const int col = (cb - d.startblk[s]) * 256 + threadIdx.x;

    float acc = 0.f;
    const int k0 = kc * 128;
    #pragma unroll 8
    for (int k = k0; k < k0 + 128; k++)
        acc += bet[k] * W[(size_t)k * N + col];
    part[kc * 6144 + cb * 256 + threadIdx.x] = acc;
}

// ---------------------------------------------------------------------------
// bf16 GEMM: C[M,N] = A[M,K] @ Bt[N,K]^T (+bias[N]) (+res, fp32 path only)
// 128x128 tile, Ktile 32, 8 warps, 3-stage cp.async ring, ldmatrix frags.
// ---------------------------------------------------------------------------
#define GSTAGE_ELEM (128 * 40)
#define GEMM_SMEM   (3 * 2 * GSTAGE_ELEM * 2)   // 61440 bytes

template<bool OBF>
__global__ __launch_bounds__(256) void gemm_bf16(
    const __nv_bfloat16* __restrict__ A, const __nv_bfloat16* __restrict__ Bt,
    void* __restrict__ Cv, int M, int N, int K,
    const float* __restrict__ bias, const float* __restrict__ res)
{
    extern __shared__ __nv_bfloat16 dsm[];
    __nv_bfloat16* As = dsm;
    __nv_bfloat16* Bs = dsm + 3 * GSTAGE_ELEM;

    const int tid = threadIdx.x;
    const int warp = tid >> 5, lane = tid & 31;
    const int q = lane >> 2, cq = lane & 3;
    const int wm = (warp >> 2) * 64, wn = (warp & 3) * 32;
    const int bm = blockIdx.y * 128, bn = blockIdx.x * 128;

    float acc[4][4][4];
    #pragma unroll
    for (int mt = 0; mt < 4; mt++)
        #pragma unroll
        for (int nt = 0; nt < 4; nt++)
            #pragma unroll
            for (int e = 0; e < 4; e++) acc[mt][nt][e] = 0.f;

    const int lr = tid >> 2;
    const int lc = (tid & 3) * 8;

    auto load_tile = [&](int kt, int st) {
        const __nv_bfloat16* Ag = A + (size_t)bm * K + kt * 32 + lc;
        const __nv_bfloat16* Bg = Bt + (size_t)bn * K + kt * 32 + lc;
        __nv_bfloat16* as = As + st * GSTAGE_ELEM;
        __nv_bfloat16* bs = Bs + st * GSTAGE_ELEM;
        cp16(su32(as + lr * 40 + lc),        Ag + (size_t)lr * K);
        cp16(su32(as + (lr + 64) * 40 + lc), Ag + (size_t)(lr + 64) * K);
        cp16(su32(bs + lr * 40 + lc),        Bg + (size_t)lr * K);
        cp16(su32(bs + (lr + 64) * 40 + lc), Bg + (size_t)(lr + 64) * K);
    };

    const int KT = K / 32;
    load_tile(0, 0); cp_commit();
    load_tile(1, 1); cp_commit();

    for (int kt = 0; kt < KT; kt++) {
        if (kt + 2 < KT) { load_tile(kt + 2, (kt + 2) % 3); cp_commit(); cp_wait<2>(); }
        else if (kt + 1 < KT) cp_wait<1>();
        else cp_wait<0>();
        __syncthreads();

        const __nv_bfloat16* as = As + (kt % 3) * GSTAGE_ELEM;
        const __nv_bfloat16* bs = Bs + (kt % 3) * GSTAGE_ELEM;
        #pragma unroll
        for (int ks = 0; ks < 2; ks++) {
            uint32_t af[4][4], bfr[2][4];
            #pragma unroll
            for (int mt = 0; mt < 4; mt++) {
                const int row = wm + mt * 16 + ((lane >> 3) & 1) * 8 + (lane & 7);
                const int col = ks * 16 + (lane >> 4) * 8;
                ldm_x4(af[mt], su32(as + row * 40 + col));
            }
            #pragma unroll
            for (int pn = 0; pn < 2; pn++) {
                const int row = wn + pn * 16 + (lane >> 4) * 8 + (lane & 7);
                const int col = ks * 16 + ((lane >> 3) & 1) * 8;
                ldm_x4(bfr[pn], su32(bs + row * 40 + col));
            }
            #pragma unroll
            for (int mt = 0; mt < 4; mt++)
                #pragma unroll
                for (int nt = 0; nt < 4; nt++)
                    mma_bf16(acc[mt][nt], af[mt], &bfr[nt >> 1][(nt & 1) * 2]);
        }
        __syncthreads();
    }

    #pragma unroll
    for (int mt = 0; mt < 4; mt++) {
        #pragma unroll
        for (int nt = 0; nt < 4; nt++) {
            const int c0 = bn + wn + nt * 8 + 2 * cq;
            #pragma unroll
            for (int half = 0; half < 2; half++) {
                const int row = bm + wm + mt * 16 + q + half * 8;
                float v0 = acc[mt][nt][half * 2 + 0];
                float v1 = acc[mt][nt][half * 2 + 1];
                if (bias) { v0 += bias[c0]; v1 += bias[c0 + 1]; }
                const size_t base = (size_t)row * N + c0;
                if (OBF) {
                    __nv_bfloat16* C = (__nv_bfloat16*)Cv;
                    *(uint32_t*)(C + base) = packbf(v0, v1);
                } else {
                    float* C = (float*)Cv;
                    if (res) { v0 += res[base]; v1 += res[base + 1]; }
                    *(float2*)(C + base) = make_float2(v0, v1);
                }
            }
        }
    }
}

// ---------------------------------------------------------------------------
// Flash attention (R13 best config, restored): bf16 MMA, max-free exp2
// softmax, fused per-kt QK->exp->PV, 8 warps x 16 rows, j-chunk 128 with
// 2-stage ring in dynamic smem (~76KB), (256,2) occupancy.
// ---------------------------------------------------------------------------
#define AKV_ELEM  (128 * 72)                 // one K or V stage (bf16 elems)
#define ATTN_SMEM (4 * AKV_ELEM * 2 + 2 * 256 * 4 + 16)   // ~75.8 KB

template<int QSTR, int KVSTR>
__global__ __launch_bounds__(256, 2) void attn_bf16(
    const __nv_bfloat16* __restrict__ qb, const __nv_bfloat16* __restrict__ kvb,
    __nv_bfloat16* __restrict__ ob, const float* __restrict__ tbl,
    int n, int m, int mnoff)
{
    extern __shared__ __nv_bfloat16 adsm[];
    __nv_bfloat16* Ksd = adsm;                    // 2 stages of 128x72
    __nv_bfloat16* Vsd = adsm + 2 * AKV_ELEM;     // 2 stages
    float* sbf = (float*)(adsm + 4 * AKV_ELEM);   // 2 x 256

    const int tid = threadIdx.x;
    const int warp = tid >> 5, lane = tid & 31;
    const int q = lane >> 2, cq = lane & 3;
    const int b = blockIdx.z, h = blockIdx.y;
    const int q0 = blockIdx.x * 128;
    const int r0l = warp * 16 + q;     // 0..127
    const int r1l = r0l + 8;
    const float* tblh = tbl + h * 4096;

    uint32_t qf[4][4];
    {
        const __nv_bfloat16* qr0 = qb + (size_t)(b * n + q0 + r0l) * QSTR + h * HDIM;
        const __nv_bfloat16* qr1 = qr0 + 8 * (size_t)QSTR;
        #pragma unroll
        for (int ks = 0; ks < 4; ks++) {
            qf[ks][0] = *(const uint32_t*)(qr0 + ks * 16 + cq * 2);
            qf[ks][1] = *(const uint32_t*)(qr1 + ks * 16 + cq * 2);
            qf[ks][2] = *(const uint32_t*)(qr0 + ks * 16 + cq * 2 + 8);
            qf[ks][3] = *(const uint32_t*)(qr1 + ks * 16 + cq * 2 + 8);
        }
    }

    float o[8][4];
    #pragma unroll
    for (int dt = 0; dt < 8; dt++)
        #pragma unroll
        for (int e = 0; e < 4; e++) o[dt][e] = 0.f;
    float l0p = 0.f, l1p = 0.f;        // per-lane partial row sums

    const __nv_bfloat16* kvbase = kvb + (size_t)(b * m) * KVSTR + h * HDIM;
    const int lr0 = tid >> 3;          // 0..31
    const int lc8 = (tid & 7) * 8;

    auto load_kv = [&](int c, int bi) {
        const __nv_bfloat16* kg = kvbase + (size_t)(c * 128) * KVSTR;
        __nv_bfloat16* kd = Ksd + bi * AKV_ELEM;
        __nv_bfloat16* vd = Vsd + bi * AKV_ELEM;
        #pragma unroll
        for (int i = 0; i < 4; i++) {
            const int r = lr0 + i * 32;               // 0..127
            cp16(su32(kd + r * 72 + lc8), kg + (size_t)r * KVSTR + lc8);
            cp16(su32(vd + r * 72 + lc8), kg + MID + (size_t)r * KVSTR + lc8);
        }
    };

    const int C = m / 128;             // self: 16, cross: 4
    const int sbase = 2048 - q0 - mnoff - 127;
    load_kv(0, 0); cp_commit();
    if (tid < 255) sbf[tid] = tblh[sbase + tid];

    for (int c = 0; c < C; c++) {
        cp_wait<0>();
        __syncthreads();   // chunk c data + bias slice visible; all past chunk c-1 reads

        if (c + 1 < C) {
            load_kv(c + 1, (c + 1) & 1);
            cp_commit();
            if (tid < 255)
                sbf[((c + 1) & 1) * 256 + tid] = tblh[sbase + (c + 1) * 128 + tid];
        }

        const __nv_bfloat16* ks_b = Ksd + (c & 1) * AKV_ELEM;
        const __nv_bfloat16* vs_b = Vsd + (c & 1) * AKV_ELEM;
        const float* sbc = sbf + (c & 1) * 256;

        // ---- per-kt (16 j columns, 8 kts): QK over 64 dims -> exp -> PV ----
        #pragma unroll
        for (int kt = 0; kt < 8; kt++) {
            float s2[2][4];
            #pragma unroll
            for (int half = 0; half < 2; half++)
                #pragma unroll
                for (int e = 0; e < 4; e++) s2[half][e] = 0.f;

            #pragma unroll
            for (int ks = 0; ks < 4; ks++) {
                uint32_t bfr[4];
                const int row = kt * 16 + (lane >> 4) * 8 + (lane & 7);
                const int col = ks * 16 + ((lane >> 3) & 1) * 8;
                ldm_x4(bfr, su32(ks_b + row * 72 + col));
                mma_bf16(s2[0], qf[ks], &bfr[0]);
                mma_bf16(s2[1], qf[ks], &bfr[2]);
            }

            // exp2(s*CC + bias)
            #pragma unroll
            for (int half = 0; half < 2; half++) {
                #pragma unroll
                for (int e = 0; e < 2; e++) {
                    const int jl = (2 * kt + half) * 8 + 2 * cq + e;
                    const float p0 = exp2a(fmaf(s2[half][e],     CC, sbc[jl - r0l + 127]));
                    const float p1 = exp2a(fmaf(s2[half][2 + e], CC, sbc[jl - r1l + 127]));
                    s2[half][e]     = p0;
                    s2[half][2 + e] = p1;
                    l0p += p0;
                    l1p += p1;
                }
            }

            // PV
            uint32_t ap[4];
            ap[0] = packbf(s2[0][0], s2[0][1]);
            ap[1] = packbf(s2[0][2], s2[0][3]);
            ap[2] = packbf(s2[1][0], s2[1][1]);
            ap[3] = packbf(s2[1][2], s2[1][3]);
            #pragma unroll
            for (int dp = 0; dp < 4; dp++) {
                uint32_t bv[4];
                const int row = kt * 16 + ((lane >> 3) & 1) * 8 + (lane & 7);
                const int col = dp * 16 + (lane >> 4) * 8;
                ldm_x4_t(bv, su32(vs_b + row * 72 + col));
                mma_bf16(o[2 * dp],     ap, &bv[0]);
                mma_bf16(o[2 * dp + 1], ap, &bv[2]);
            }
        }
        // next iteration's barrier orders buffer reuse
    }

    // deferred row-sum reduction over the 4 cq lanes
    l0p += __shfl_xor_sync(0xffffffffu, l0p, 1);
    l0p += __shfl_xor_sync(0xffffffffu, l0p, 2);
    l1p += __shfl_xor_sync(0xffffffffu, l1p, 1);
    l1p += __shfl_xor_sync(0xffffffffu, l1p, 2);

    const float inv0 = 1.0f / l0p;
    const float inv1 = 1.0f / l1p;
    __nv_bfloat16* or0 = ob + (size_t)(b * n + q0 + r0l) * MID + h * HDIM;
    __nv_bfloat16* or1 = ob + (size_t)(b * n + q0 + r1l) * MID + h * HDIM;
    #pragma unroll
    for (int dt = 0; dt < 8; dt++) {
        const int cc2 = dt * 8 + 2 * cq;
        *(uint32_t*)(or0 + cc2) = packbf(o[dt][0] * inv0, o[dt][1] * inv0);
        *(uint32_t*)(or1 + cc2) = packbf(o[dt][2] * inv1, o[dt][3] * inv1);
    }
}

// ---------------------------------------------------------------------------
// Launch
// ---------------------------------------------------------------------------
extern "C" void kernel_launch(void* const* d_in, const int* in_sizes, int n_in,
                              void* d_out, int out_size)
{
    (void)in_sizes; (void)n_in; (void)out_size;

    const float* x       = (const float*)d_in[0];
    const float* ctx     = (const float*)d_in[1];
    const float* sa_ng   = (const float*)d_in[2];
    const float* sa_nb   = (const float*)d_in[3];
    const float* sa_ncg  = (const float*)d_in[4];
    const float* sa_ncb  = (const float*)d_in[5];
    const float* sa_wq   = (const float*)d_in[6];
    const float* sa_wkv  = (const float*)d_in[7];
    const float* sa_wo   = (const float*)d_in[8];
    const float* sa_bo   = (const float*)d_in[9];
    const float* sa_rel  = (const float*)d_in[10];
    const float* ca_ng   = (const float*)d_in[11];
    const float* ca_nb   = (const float*)d_in[12];
    const float* ca_ncg  = (const float*)d_in[13];
    const float* ca_ncb  = (const float*)d_in[14];
    const float* ca_wq   = (const float*)d_in[15];
    const float* ca_wkv  = (const float*)d_in[16];
    const float* ca_wo   = (const float*)d_in[17];
    const float* ca_bo   = (const float*)d_in[18];
    const float* ca_rel  = (const float*)d_in[19];
    float* out = (float*)d_out;

    __nv_bfloat16 *xh, *ch, *qkv, *qc, *kvc, *ao, *wqkv, *wto, *wtq2, *wtkv2, *wto2;
    float *x1, *tbl, *bvec, *bpart;
    cudaGetSymbolAddress((void**)&xh,    g_xh);
    cudaGetSymbolAddress((void**)&ch,    g_ch);
    cudaGetSymbolAddress((void**)&qkv,   g_qkv);
    cudaGetSymbolAddress((void**)&qc,    g_qc);
    cudaGetSymbolAddress((void**)&kvc,   g_kvc);
    cudaGetSymbolAddress((void**)&ao,    g_ao);
    cudaGetSymbolAddress((void**)&x1,    g_x1);
    cudaGetSymbolAddress((void**)&tbl,   g_tbl);
    cudaGetSymbolAddress((void**)&bvec,  g_bvec);
    cudaGetSymbolAddress((void**)&bpart, g_bpart);
    cudaGetSymbolAddress((void**)&wqkv,  g_wqkv);
    cudaGetSymbolAddress((void**)&wto,   g_wto);
    cudaGetSymbolAddress((void**)&wtq2,  g_wtq2);
    cudaGetSymbolAddress((void**)&wtkv2, g_wtkv2);
    cudaGetSymbolAddress((void**)&wto2,  g_wto2);

    cudaFuncSetAttribute(gemm_bf16<true>,  cudaFuncAttributeMaxDynamicSharedMemorySize, GEMM_SMEM);
    cudaFuncSetAttribute(gemm_bf16<false>, cudaFuncAttributeMaxDynamicSharedMemorySize, GEMM_SMEM);
    cudaFuncSetAttribute(attn_bf16<3 * MID, 3 * MID>, cudaFuncAttributeMaxDynamicSharedMemorySize, ATTN_SMEM);
    cudaFuncSetAttribute(attn_bf16<MID, 2 * MID>,     cudaFuncAttributeMaxDynamicSharedMemorySize, ATTN_SMEM);

    // ---- prep: folded weight transposes, bias rows (split-k), rel tables ----
    WDesc wd;
    wd.W[0] = sa_wq;  wd.G[0] = sa_ng;  wd.Wt[0] = wqkv;            wd.K[0] = F;   wd.N[0] = MID;
    wd.W[1] = sa_wkv; wd.G[1] = sa_ncg; wd.Wt[1] = wqkv + MID * F;  wd.K[1] = F;   wd.N[1] = 2 * MID;
    wd.W[2] = sa_wo;  wd.G[2] = nullptr;wd.Wt[2] = wto;             wd.K[2] = MID; wd.N[2] = F;
    wd.W[3] = ca_wq;  wd.G[3] = ca_ng;  wd.Wt[3] = wtq2;            wd.K[3] = F;   wd.N[3] = MID;
    wd.W[4] = ca_wkv; wd.G[4] = ca_ncg; wd.Wt[4] = wtkv2;           wd.K[4] = F;   wd.N[4] = 2 * MID;
    wd.W[5] = ca_wo;  wd.G[5] = nullptr;wd.Wt[5] = wto2;            wd.K[5] = MID; wd.N[5] = F;
    int cum = 0;
    for (int i = 0; i < 6; i++) {
        wd.start[i] = cum;
        cum += (wd.N[i] / 32) * (wd.K[i] / 32);
    }
    wd.start[6] = cum;
    wtrans_all_kernel<<<cum, dim3(32, 8)>>>(wd);

    BDesc bd;
    bd.b[0] = sa_nb;  bd.W[0] = sa_wq;  bd.N[0] = MID;
    bd.b[1] = sa_ncb; bd.W[1] = sa_wkv; bd.N[1] = 2 * MID;
    bd.b[2] = ca_nb;  bd.W[2] = ca_wq;  bd.N[2] = MID;
    bd.b[3] = ca_ncb; bd.W[3] = ca_wkv; bd.N[3] = 2 * MID;
    int bcum = 0;
    for (int i = 0; i < 4; i++) { bd.startblk[i] = bcum; bcum += bd.N[i] / 256; }
    bd.startblk[4] = bcum;
    bvec_part_kernel<<<dim3(bcum, 8), 256>>>(bd, bpart);

    // fused: rel-pos tables (512 blocks) + bvec reduce (bcum blocks)
    bias2_sum_kernel<<<512 + bcum, 256>>>(sa_rel, ca_rel, tbl, bpart, bvec, bcum);

    // ---------------- self-attention ----------------
    lnw_kernel<<<ROWS_X / 8, 256>>>(x, xh);
    gemm_bf16<true ><<<dim3(3 * MID / 128, ROWS_X / 128), 256, GEMM_SMEM>>>(
        xh, wqkv, qkv, ROWS_X, 3 * MID, F, bvec, nullptr);
    attn_bf16<3 * MID, 3 * MID><<<dim3(NQ / 128, NHEAD, B), 256, ATTN_SMEM>>>(
        qkv, qkv + MID, ao, tbl, NQ, NQ, 0);
    gemm_bf16<false><<<dim3(F / 128, ROWS_X / 128), 256, GEMM_SMEM>>>(
        ao, wto, x1, ROWS_X, F, MID, sa_bo, x);

    // ---------------- cross-attention ----------------
    lnw2_kernel<<<ROWS_X / 8 + ROWS_C / 8, 256>>>(x1, xh, ROWS_X / 8, ctx, ch);
    gemm_bf16<true ><<<dim3(MID / 128, ROWS_X / 128), 256, GEMM_SMEM>>>(
        xh, wtq2, qc, ROWS_X, MID, F, bvec + 3 * MID, nullptr);
    gemm_bf16<true ><<<dim3(2 * MID / 128, ROWS_C / 128), 256, GEMM_SMEM>>>(
        ch, wtkv2, kvc, ROWS_C, 2 * MID, F, bvec + 4 * MID, nullptr);
    attn_bf16<MID, 2 * MID><<<dim3(NQ / 128, NHEAD, B), 256, ATTN_SMEM>>>(
        qc, kvc, ao, tbl + NHEAD * 4096, NQ, NCTX, NCTX - NQ);
    gemm_bf16<false><<<dim3(F / 128, ROWS_X / 128), 256, GEMM_SMEM>>>(
        ao, wto2, out, ROWS_X, F, MID, ca_bo, x1);
}

// round 16
// speedup vs baseline: 1.6135x; 1.0414x over previous
#include <cuda_runtime.h>
#include <cuda_bf16.h>
#include <math.h>
#include <math_constants.h>
#include <stdint.h>

// ---------------------------------------------------------------------------
// Problem constants
// ---------------------------------------------------------------------------
#define B        2
#define NQ       2048
#define NCTX     512
#define F        1024
#define MID      1024
#define NHEAD    16
#define HDIM     64
#define ROWS_X   (B * NQ)      // 4096
#define ROWS_C   (B * NCTX)    // 1024

// exp((s+b)*0.125) = 2^(s*CC + b*CC) ; bias table is pre-multiplied by CC
#define CC 0.18033688011112042f   // 0.125 * log2(e)

// ---------------------------------------------------------------------------
// Scratch (device globals)
// ---------------------------------------------------------------------------
__device__ __nv_bfloat16 g_xh  [ROWS_X * F];
__device__ __nv_bfloat16 g_ch  [ROWS_C * F];
__device__ __nv_bfloat16 g_qkv [ROWS_X * 3 * MID];    // self merged [q|k|v]
__device__ __nv_bfloat16 g_qc  [ROWS_X * MID];
__device__ __nv_bfloat16 g_kvc [ROWS_C * 2 * MID];
__device__ __nv_bfloat16 g_ao  [ROWS_X * MID];
__device__ float         g_x1  [ROWS_X * F];
__device__ float         g_tbl [2 * NHEAD * 4096];    // pre-scaled by CC
__device__ float         g_bvec[6144];
__device__ float         g_bpart[8 * 6144];
__device__ __nv_bfloat16 g_wqkv [3 * MID * F];
__device__ __nv_bfloat16 g_wto  [F * MID];
__device__ __nv_bfloat16 g_wtq2 [MID * F];
__device__ __nv_bfloat16 g_wtkv2[2 * MID * F];
__device__ __nv_bfloat16 g_wto2 [F * MID];

// ---------------------------------------------------------------------------
// PTX helpers
// ---------------------------------------------------------------------------
__device__ __forceinline__ uint32_t su32(const void* p) {
    return (uint32_t)__cvta_generic_to_shared(p);
}
__device__ __forceinline__ void cp16(uint32_t dst, const void* src) {
    asm volatile("cp.async.cg.shared.global [%0], [%1], 16;" :: "r"(dst), "l"(src));
}
__device__ __forceinline__ void cp_commit() {
    asm volatile("cp.async.commit_group;");
}
template<int N> __device__ __forceinline__ void cp_wait() {
    asm volatile("cp.async.wait_group %0;" :: "n"(N));
}
__device__ __forceinline__ void ldm_x4(uint32_t r[4], uint32_t addr) {
    asm volatile("ldmatrix.sync.aligned.m8n8.x4.shared.b16 {%0,%1,%2,%3}, [%4];"
                 : "=r"(r[0]), "=r"(r[1]), "=r"(r[2]), "=r"(r[3]) : "r"(addr));
}
__device__ __forceinline__ void ldm_x4_t(uint32_t r[4], uint32_t addr) {
    asm volatile("ldmatrix.sync.aligned.m8n8.x4.trans.shared.b16 {%0,%1,%2,%3}, [%4];"
                 : "=r"(r[0]), "=r"(r[1]), "=r"(r[2]), "=r"(r[3]) : "r"(addr));
}
__device__ __forceinline__ void mma_bf16(float c[4], const uint32_t a[4], const uint32_t b[2]) {
    asm volatile(
        "mma.sync.aligned.m16n8k16.row.col.f32.bf16.bf16.f32 "
        "{%0,%1,%2,%3}, {%4,%5,%6,%7}, {%8,%9}, {%0,%1,%2,%3};\n"
        : "+f"(c[0]), "+f"(c[1]), "+f"(c[2]), "+f"(c[3])
        : "r"(a[0]), "r"(a[1]), "r"(a[2]), "r"(a[3]), "r"(b[0]), "r"(b[1]));
}
__device__ __forceinline__ uint32_t packbf(float lo, float hi) {
    __nv_bfloat162 t = __floats2bfloat162_rn(lo, hi);
    return *reinterpret_cast<uint32_t*>(&t);
}
__device__ __forceinline__ float exp2a(float x) {
    float y;
    asm("ex2.approx.ftz.f32 %0, %1;" : "=f"(y) : "f"(x));
    return y;
}

// ---------------------------------------------------------------------------
// LN-hat, warp-per-row: x -> (x-mean)*rsqrt(var+eps) bf16. Single pass.
// ---------------------------------------------------------------------------
__device__ __forceinline__ void lnw_row(
    const float* __restrict__ x, __nv_bfloat16* __restrict__ out,
    int row, int lane)
{
    const float4* xr = (const float4*)(x + (size_t)row * F);
    float4 v[8];
    #pragma unroll
    for (int i = 0; i < 8; i++) v[i] = xr[lane + 32 * i];

    float s = 0.f, s2 = 0.f;
    #pragma unroll
    for (int i = 0; i < 8; i++) {
        s  += v[i].x + v[i].y + v[i].z + v[i].w;
        s2 += v[i].x * v[i].x + v[i].y * v[i].y + v[i].z * v[i].z + v[i].w * v[i].w;
    }
    #pragma unroll
    for (int o = 16; o > 0; o >>= 1) {
        s  += __shfl_xor_sync(0xffffffffu, s,  o);
        s2 += __shfl_xor_sync(0xffffffffu, s2, o);
    }
    const float mean = s * (1.0f / F);
    const float var  = s2 * (1.0f / F) - mean * mean;
    const float rs   = rsqrtf(var + 1e-5f);

    __nv_bfloat16* orow = out + (size_t)row * F;
    #pragma unroll
    for (int i = 0; i < 8; i++) {
        __nv_bfloat162 p0 = __floats2bfloat162_rn((v[i].x - mean) * rs, (v[i].y - mean) * rs);
        __nv_bfloat162 p1 = __floats2bfloat162_rn((v[i].z - mean) * rs, (v[i].w - mean) * rs);
        uint2 u = make_uint2(*(uint32_t*)&p0, *(uint32_t*)&p1);
        *(uint2*)(orow + (lane + 32 * i) * 4) = u;
    }
}

__global__ __launch_bounds__(256) void lnw_kernel(
    const float* __restrict__ x, __nv_bfloat16* __restrict__ out)
{
    const int row  = (blockIdx.x * 256 + threadIdx.x) >> 5;
    lnw_row(x, out, row, threadIdx.x & 31);
}

// merged two-input LN: blocks [0, nb1) process x1->o1, rest process x2->o2
__global__ __launch_bounds__(256) void lnw2_kernel(
    const float* __restrict__ x1, __nv_bfloat16* __restrict__ o1, int nb1,
    const float* __restrict__ x2, __nv_bfloat16* __restrict__ o2)
{
    const int lane = threadIdx.x & 31;
    if (blockIdx.x < (unsigned)nb1) {
        const int row = (blockIdx.x * 256 + threadIdx.x) >> 5;
        lnw_row(x1, o1, row, lane);
    } else {
        const int row = (((blockIdx.x - nb1) * 256) + threadIdx.x) >> 5;
        lnw_row(x2, o2, row, lane);
    }
}

// ---------------------------------------------------------------------------
// Prep fused tail: rel-pos tables (blocks 0..511) + bvec reduce (blocks 512+)
// ---------------------------------------------------------------------------
__global__ __launch_bounds__(256) void bias2_sum_kernel(
    const float* __restrict__ e0, const float* __restrict__ e1,
    float* __restrict__ tbl,
    const float* __restrict__ part, float* __restrict__ bout, int nb_sum)
{
    if (blockIdx.x < 512) {
        const int idx = blockIdx.x * 256 + threadIdx.x;
        const float* emb = (idx < 65536) ? e0 : e1;
        const int li = idx & 65535;
        const int h = li >> 12;
        const int p = li & 4095;
        const int rel = p - 2048;
        const int retv = (rel >= 0) ? 16 : 0;
        const int na = (rel < 0) ? -rel : rel;
        int bucket;
        if (na < 8) {
            bucket = retv + na;
        } else {
            float t = logf((float)na * 0.125f) / 2.7725887f;   // log(16)
            int vl = 8 + (int)(t * 8.0f);
            bucket = retv + min(vl, 15);
        }
        tbl[idx] = emb[bucket * NHEAD + h] * CC;
    } else {
        const int bi = blockIdx.x - 512;
        if (bi < nb_sum) {
            const int i = bi * 256 + threadIdx.x;
            float a = 0.f;
            #pragma unroll
            for (int j = 0; j < 8; j++) a += part[j * 6144 + i];
            bout[i] = a;
        }
    }
}

// ---------------------------------------------------------------------------
// All 6 weight transposes (with optional gamma fold) in one segmented launch.
// ---------------------------------------------------------------------------
struct WDesc {
    const float* W[6];
    const float* G[6];
    __nv_bfloat16* Wt[6];
    int K[6], N[6];
    int start[7];
};

__global__ __launch_bounds__(256) void wtrans_all_kernel(WDesc d)
{
    __shared__ float t[32][33];
    const int bid = blockIdx.x;
    int s = 0;
    #pragma unroll
    for (int i = 1; i < 6; i++) if (bid >= d.start[i]) s = i;

    const float* W = d.W[s];
    const float* G = d.G[s];
    __nv_bfloat16* Wt = d.Wt[s];
    const int K = d.K[s], N = d.N[s];
    const int bi = bid - d.start[s];
    const int nbx = N >> 5;
    const int n0 = (bi % nbx) * 32;
    const int k0 = (bi / nbx) * 32;

    const int tx = threadIdx.x, ty = threadIdx.y;
    #pragma unroll
    for (int i = 0; i < 4; i++)
        t[ty + 8 * i][tx] = W[(size_t)(k0 + ty + 8 * i) * N + n0 + tx];
    __syncthreads();
    const float gv = G ? G[k0 + tx] : 1.0f;
    #pragma unroll
    for (int i = 0; i < 4; i++)
        Wt[(size_t)(n0 + ty + 8 * i) * K + k0 + tx] = __float2bfloat16(t[tx][ty + 8 * i] * gv);
}

// ---------------------------------------------------------------------------
// Bias rows split-k partials: part[kc][n] = sum_{k in chunk} beta[k]*W[k][n]
// ---------------------------------------------------------------------------
struct BDesc {
    const float* b[4];
    const float* W[4];
    int N[4];
    int startblk[5];
};

__global__ __launch_bounds__(256) void bvec_part_kernel(BDesc d, float* __restrict__ part)
{
    const int cb = blockIdx.x;
    const int kc = blockIdx.y;
    int s = 0;
    #pragma unroll
    for (int i = 1; i < 4; i++) if (cb >= d.startblk[i]) s = i;
    const float* bet = d.b[s];
    const float* W = d.W[s];
    const int N = d.N[s];
    const int col = (cb - d.startblk[s]) * 256 + threadIdx.x;

    float acc = 0.f;
    const int k0 = kc * 128;
    #pragma unroll 8
    for (int k = k0; k < k0 + 128; k++)
        acc += bet[k] * W[(size_t)k * N + col];
    part[kc * 6144 + cb * 256 + threadIdx.x] = acc;
}

// ---------------------------------------------------------------------------
// bf16 GEMM body: C[M,N] tile (bm,bn) = A[M,K] @ Bt[N,K]^T (+bias) (+res).
// 128x128 tile, Ktile 32, 8 warps, 3-stage cp.async ring, ldmatrix frags.
// ---------------------------------------------------------------------------
#define GSTAGE_ELEM (128 * 40)
#define GEMM_SMEM   (3 * 2 * GSTAGE_ELEM * 2)   // 61440 bytes

template<bool OBF>
__device__ __forceinline__ void gemm_body(
    const __nv_bfloat16* __restrict__ A, const __nv_bfloat16* __restrict__ Bt,
    void* __restrict__ Cv, int N, int K,
    const float* __restrict__ bias, const float* __restrict__ res,
    int bm, int bn, __nv_bfloat16* dsm)
{
    __nv_bfloat16* As = dsm;
    __nv_bfloat16* Bs = dsm + 3 * GSTAGE_ELEM;

    const int tid = threadIdx.x;
    const int warp = tid >> 5, lane = tid & 31;
    const int q = lane >> 2, cq = lane & 3;
    const int wm = (warp >> 2) * 64, wn = (warp & 3) * 32;

    float acc[4][4][4];
    #pragma unroll
    for (int mt = 0; mt < 4; mt++)
        #pragma unroll
        for (int nt = 0; nt < 4; nt++)
            #pragma unroll
            for (int e = 0; e < 4; e++) acc[mt][nt][e] = 0.f;

    const int lr = tid >> 2;
    const int lc = (tid & 3) * 8;

    auto load_tile = [&](int kt, int st) {
        const __nv_bfloat16* Ag = A + (size_t)bm * K + kt * 32 + lc;
        const __nv_bfloat16* Bg = Bt + (size_t)bn * K + kt * 32 + lc;
        __nv_bfloat16* as = As + st * GSTAGE_ELEM;
        __nv_bfloat16* bs = Bs + st * GSTAGE_ELEM;
        cp16(su32(as + lr * 40 + lc),        Ag + (size_t)lr * K);
        cp16(su32(as + (lr + 64) * 40 + lc), Ag + (size_t)(lr + 64) * K);
        cp16(su32(bs + lr * 40 + lc),        Bg + (size_t)lr * K);
        cp16(su32(bs + (lr + 64) * 40 + lc), Bg + (size_t)(lr + 64) * K);
    };

    const int KT = K / 32;
    load_tile(0, 0); cp_commit();
    load_tile(1, 1); cp_commit();

    for (int kt = 0; kt < KT; kt++) {
        if (kt + 2 < KT) { load_tile(kt + 2, (kt + 2) % 3); cp_commit(); cp_wait<2>(); }
        else if (kt + 1 < KT) cp_wait<1>();
        else cp_wait<0>();
        __syncthreads();

        const __nv_bfloat16* as = As + (kt % 3) * GSTAGE_ELEM;
        const __nv_bfloat16* bs = Bs + (kt % 3) * GSTAGE_ELEM;
        #pragma unroll
        for (int ks = 0; ks < 2; ks++) {
            uint32_t af[4][4], bfr[2][4];
            #pragma unroll
            for (int mt = 0; mt < 4; mt++) {
                const int row = wm + mt * 16 + ((lane >> 3) & 1) * 8 + (lane & 7);
                const int col = ks * 16 + (lane >> 4) * 8;
                ldm_x4(af[mt], su32(as + row * 40 + col));
            }
            #pragma unroll
            for (int pn = 0; pn < 2; pn++) {
                const int row = wn + pn * 16 + (lane >> 4) * 8 + (lane & 7);
                const int col = ks * 16 + ((lane >> 3) & 1) * 8;
                ldm_x4(bfr[pn], su32(bs + row * 40 + col));
            }
            #pragma unroll
            for (int mt = 0; mt < 4; mt++)
                #pragma unroll
                for (int nt = 0; nt < 4; nt++)
                    mma_bf16(acc[mt][nt], af[mt], &bfr[nt >> 1][(nt & 1) * 2]);
        }
        __syncthreads();
    }

    #pragma unroll
    for (int mt = 0; mt < 4; mt++) {
        #pragma unroll
        for (int nt = 0; nt < 4; nt++) {
            const int c0 = bn + wn + nt * 8 + 2 * cq;
            #pragma unroll
            for (int half = 0; half < 2; half++) {
                const int row = bm + wm + mt * 16 + q + half * 8;
                float v0 = acc[mt][nt][half * 2 + 0];
                float v1 = acc[mt][nt][half * 2 + 1];
                if (bias) { v0 += bias[c0]; v1 += bias[c0 + 1]; }
                const size_t base = (size_t)row * N + c0;
                if (OBF) {
                    __nv_bfloat16* C = (__nv_bfloat16*)Cv;
                    *(uint32_t*)(C + base) = packbf(v0, v1);
                } else {
                    float* C = (float*)Cv;
                    if (res) { v0 += res[base]; v1 += res[base + 1]; }
                    *(float2*)(C + base) = make_float2(v0, v1);
                }
            }
        }
    }
}

template<bool OBF>
__global__ __launch_bounds__(256) void gemm_bf16(
    const __nv_bfloat16* __restrict__ A, const __nv_bfloat16* __restrict__ Bt,
    void* __restrict__ Cv, int M, int N, int K,
    const float* __restrict__ bias, const float* __restrict__ res)
{
    extern __shared__ __nv_bfloat16 dsm[];
    gemm_body<OBF>(A, Bt, Cv, N, K, bias, res,
                   blockIdx.y * 128, blockIdx.x * 128, dsm);
}

// dual GEMM (both bf16-out): blocks [0, nb1) run gemm 1, rest run gemm 2.
__global__ __launch_bounds__(256) void gemm_dual_kernel(
    const __nv_bfloat16* A1, const __nv_bfloat16* B1, __nv_bfloat16* C1,
    int N1, int nx1, int nb1, const float* bias1,
    const __nv_bfloat16* A2, const __nv_bfloat16* B2, __nv_bfloat16* C2,
    int N2, int nx2, const float* bias2, int K)
{
    extern __shared__ __nv_bfloat16 dsm[];
    const int bid = blockIdx.x;
    if (bid < nb1) {
        gemm_body<true>(A1, B1, C1, N1, K, bias1, nullptr,
                        (bid / nx1) * 128, (bid % nx1) * 128, dsm);
    } else {
        const int b2 = bid - nb1;
        gemm_body<true>(A2, B2, C2, N2, K, bias2, nullptr,
                        (b2 / nx2) * 128, (b2 % nx2) * 128, dsm);
    }
}

// ---------------------------------------------------------------------------
// Flash attention (R13/R15 best config): bf16 MMA, max-free exp2 softmax,
// fused per-kt QK->exp->PV, 8 warps x 16 rows, j-chunk 128, 2-stage ring in
// dynamic smem (~76KB), (256,2) occupancy.
// ---------------------------------------------------------------------------
#define AKV_ELEM  (128 * 72)                 // one K or V stage (bf16 elems)
#define ATTN_SMEM (4 * AKV_ELEM * 2 + 2 * 256 * 4 + 16)   // ~75.8 KB

template<int QSTR, int KVSTR>
__global__ __launch_bounds__(256, 2) void attn_bf16(
    const __nv_bfloat16* __restrict__ qb, const __nv_bfloat16* __restrict__ kvb,
    __nv_bfloat16* __restrict__ ob, const float* __restrict__ tbl,
    int n, int m, int mnoff)
{
    extern __shared__ __nv_bfloat16 adsm[];
    __nv_bfloat16* Ksd = adsm;                    // 2 stages of 128x72
    __nv_bfloat16* Vsd = adsm + 2 * AKV_ELEM;     // 2 stages
    float* sbf = (float*)(adsm + 4 * AKV_ELEM);   // 2 x 256

    const int tid = threadIdx.x;
    const int warp = tid >> 5, lane = tid & 31;
    const int q = lane >> 2, cq = lane & 3;
    const int b = blockIdx.z, h = blockIdx.y;
    const int q0 = blockIdx.x * 128;
    const int r0l = warp * 16 + q;     // 0..127
    const int r1l = r0l + 8;
    const float* tblh = tbl + h * 4096;

    uint32_t qf[4][4];
    {
        const __nv_bfloat16* qr0 = qb + (size_t)(b * n + q0 + r0l) * QSTR + h * HDIM;
        const __nv_bfloat16* qr1 = qr0 + 8 * (size_t)QSTR;
        #pragma unroll
        for (int ks = 0; ks < 4; ks++) {
            qf[ks][0] = *(const uint32_t*)(qr0 + ks * 16 + cq * 2);
            qf[ks][1] = *(const uint32_t*)(qr1 + ks * 16 + cq * 2);
            qf[ks][2] = *(const uint32_t*)(qr0 + ks * 16 + cq * 2 + 8);
            qf[ks][3] = *(const uint32_t*)(qr1 + ks * 16 + cq * 2 + 8);
        }
    }

    float o[8][4];
    #pragma unroll
    for (int dt = 0; dt < 8; dt++)
        #pragma unroll
        for (int e = 0; e < 4; e++) o[dt][e] = 0.f;
    float l0p = 0.f, l1p = 0.f;        // per-lane partial row sums

    const __nv_bfloat16* kvbase = kvb + (size_t)(b * m) * KVSTR + h * HDIM;
    const int lr0 = tid >> 3;          // 0..31
    const int lc8 = (tid & 7) * 8;

    auto load_kv = [&](int c, int bi) {
        const __nv_bfloat16* kg = kvbase + (size_t)(c * 128) * KVSTR;
        __nv_bfloat16* kd = Ksd + bi * AKV_ELEM;
        __nv_bfloat16* vd = Vsd + bi * AKV_ELEM;
        #pragma unroll
        for (int i = 0; i < 4; i++) {
            const int r = lr0 + i * 32;               // 0..127
            cp16(su32(kd + r * 72 + lc8), kg + (size_t)r * KVSTR + lc8);
            cp16(su32(vd + r * 72 + lc8), kg + MID + (size_t)r * KVSTR + lc8);
        }
    };

    const int C = m / 128;             // self: 16, cross: 4
    const int sbase = 2048 - q0 - mnoff - 127;
    load_kv(0, 0); cp_commit();
    if (tid < 255) sbf[tid] = tblh[sbase + tid];

    for (int c = 0; c < C; c++) {
        cp_wait<0>();
        __syncthreads();   // chunk c data + bias slice visible; all past chunk c-1 reads

        if (c + 1 < C) {
            load_kv(c + 1, (c + 1) & 1);
            cp_commit();
            if (tid < 255)
                sbf[((c + 1) & 1) * 256 + tid] = tblh[sbase + (c + 1) * 128 + tid];
        }

        const __nv_bfloat16* ks_b = Ksd + (c & 1) * AKV_ELEM;
        const __nv_bfloat16* vs_b = Vsd + (c & 1) * AKV_ELEM;
        const float* sbc = sbf + (c & 1) * 256;

        // ---- per-kt (16 j columns, 8 kts): QK over 64 dims -> exp -> PV ----
        #pragma unroll
        for (int kt = 0; kt < 8; kt++) {
            float s2[2][4];
            #pragma unroll
            for (int half = 0; half < 2; half++)
                #pragma unroll
                for (int e = 0; e < 4; e++) s2[half][e] = 0.f;

            #pragma unroll
            for (int ks = 0; ks < 4; ks++) {
                uint32_t bfr[4];
                const int row = kt * 16 + (lane >> 4) * 8 + (lane & 7);
                const int col = ks * 16 + ((lane >> 3) & 1) * 8;
                ldm_x4(bfr, su32(ks_b + row * 72 + col));
                mma_bf16(s2[0], qf[ks], &bfr[0]);
                mma_bf16(s2[1], qf[ks], &bfr[2]);
            }

            // exp2(s*CC + bias)
            #pragma unroll
            for (int half = 0; half < 2; half++) {
                #pragma unroll
                for (int e = 0; e < 2; e++) {
                    const int jl = (2 * kt + half) * 8 + 2 * cq + e;
                    const float p0 = exp2a(fmaf(s2[half][e],     CC, sbc[jl - r0l + 127]));
                    const float p1 = exp2a(fmaf(s2[half][2 + e], CC, sbc[jl - r1l + 127]));
                    s2[half][e]     = p0;
                    s2[half][2 + e] = p1;
                    l0p += p0;
                    l1p += p1;
                }
            }

            // PV
            uint32_t ap[4];
            ap[0] = packbf(s2[0][0], s2[0][1]);
            ap[1] = packbf(s2[0][2], s2[0][3]);
            ap[2] = packbf(s2[1][0], s2[1][1]);
            ap[3] = packbf(s2[1][2], s2[1][3]);
            #pragma unroll
            for (int dp = 0; dp < 4; dp++) {
                uint32_t bv[4];
                const int row = kt * 16 + ((lane >> 3) & 1) * 8 + (lane & 7);
                const int col = dp * 16 + (lane >> 4) * 8;
                ldm_x4_t(bv, su32(vs_b + row * 72 + col));
                mma_bf16(o[2 * dp],     ap, &bv[0]);
                mma_bf16(o[2 * dp + 1], ap, &bv[2]);
            }
        }
        // next iteration's barrier orders buffer reuse
    }

    // deferred row-sum reduction over the 4 cq lanes
    l0p += __shfl_xor_sync(0xffffffffu, l0p, 1);
    l0p += __shfl_xor_sync(0xffffffffu, l0p, 2);
    l1p += __shfl_xor_sync(0xffffffffu, l1p, 1);
    l1p += __shfl_xor_sync(0xffffffffu, l1p, 2);

    const float inv0 = 1.0f / l0p;
    const float inv1 = 1.0f / l1p;
    __nv_bfloat16* or0 = ob + (size_t)(b * n + q0 + r0l) * MID + h * HDIM;
    __nv_bfloat16* or1 = ob + (size_t)(b * n + q0 + r1l) * MID + h * HDIM;
    #pragma unroll
    for (int dt = 0; dt < 8; dt++) {
        const int cc2 = dt * 8 + 2 * cq;
        *(uint32_t*)(or0 + cc2) = packbf(o[dt][0] * inv0, o[dt][1] * inv0);
        *(uint32_t*)(or1 + cc2) = packbf(o[dt][2] * inv1, o[dt][3] * inv1);
    }
}

// ---------------------------------------------------------------------------
// Launch
// ---------------------------------------------------------------------------
extern "C" void kernel_launch(void* const* d_in, const int* in_sizes, int n_in,
                              void* d_out, int out_size)
{
    (void)in_sizes; (void)n_in; (void)out_size;

    const float* x       = (const float*)d_in[0];
    const float* ctx     = (const float*)d_in[1];
    const float* sa_ng   = (const float*)d_in[2];
    const float* sa_nb   = (const float*)d_in[3];
    const float* sa_ncg  = (const float*)d_in[4];
    const float* sa_ncb  = (const float*)d_in[5];
    const float* sa_wq   = (const float*)d_in[6];
    const float* sa_wkv  = (const float*)d_in[7];
    const float* sa_wo   = (const float*)d_in[8];
    const float* sa_bo   = (const float*)d_in[9];
    const float* sa_rel  = (const float*)d_in[10];
    const float* ca_ng   = (const float*)d_in[11];
    const float* ca_nb   = (const float*)d_in[12];
    const float* ca_ncg  = (const float*)d_in[13];
    const float* ca_ncb  = (const float*)d_in[14];
    const float* ca_wq   = (const float*)d_in[15];
    const float* ca_wkv  = (const float*)d_in[16];
    const float* ca_wo   = (const float*)d_in[17];
    const float* ca_bo   = (const float*)d_in[18];
    const float* ca_rel  = (const float*)d_in[19];
    float* out = (float*)d_out;

    __nv_bfloat16 *xh, *ch, *qkv, *qc, *kvc, *ao, *wqkv, *wto, *wtq2, *wtkv2, *wto2;
    float *x1, *tbl, *bvec, *bpart;
    cudaGetSymbolAddress((void**)&xh,    g_xh);
    cudaGetSymbolAddress((void**)&ch,    g_ch);
    cudaGetSymbolAddress((void**)&qkv,   g_qkv);
    cudaGetSymbolAddress((void**)&qc,    g_qc);
    cudaGetSymbolAddress((void**)&kvc,   g_kvc);
    cudaGetSymbolAddress((void**)&ao,    g_ao);
    cudaGetSymbolAddress((void**)&x1,    g_x1);
    cudaGetSymbolAddress((void**)&tbl,   g_tbl);
    cudaGetSymbolAddress((void**)&bvec,  g_bvec);
    cudaGetSymbolAddress((void**)&bpart, g_bpart);
    cudaGetSymbolAddress((void**)&wqkv,  g_wqkv);
    cudaGetSymbolAddress((void**)&wto,   g_wto);
    cudaGetSymbolAddress((void**)&wtq2,  g_wtq2);
    cudaGetSymbolAddress((void**)&wtkv2, g_wtkv2);
    cudaGetSymbolAddress((void**)&wto2,  g_wto2);

    cudaFuncSetAttribute(gemm_bf16<true>,  cudaFuncAttributeMaxDynamicSharedMemorySize, GEMM_SMEM);
    cudaFuncSetAttribute(gemm_bf16<false>, cudaFuncAttributeMaxDynamicSharedMemorySize, GEMM_SMEM);
    cudaFuncSetAttribute(gemm_dual_kernel, cudaFuncAttributeMaxDynamicSharedMemorySize, GEMM_SMEM);
    cudaFuncSetAttribute(attn_bf16<3 * MID, 3 * MID>, cudaFuncAttributeMaxDynamicSharedMemorySize, ATTN_SMEM);
    cudaFuncSetAttribute(attn_bf16<MID, 2 * MID>,     cudaFuncAttributeMaxDynamicSharedMemorySize, ATTN_SMEM);

    // ---- prep: folded weight transposes, bias rows (split-k), rel tables ----
    WDesc wd;
    wd.W[0] = sa_wq;  wd.G[0] = sa_ng;  wd.Wt[0] = wqkv;            wd.K[0] = F;   wd.N[0] = MID;
    wd.W[1] = sa_wkv; wd.G[1] = sa_ncg; wd.Wt[1] = wqkv + MID * F;  wd.K[1] = F;   wd.N[1] = 2 * MID;
    wd.W[2] = sa_wo;  wd.G[2] = nullptr;wd.Wt[2] = wto;             wd.K[2] = MID; wd.N[2] = F;
    wd.W[3] = ca_wq;  wd.G[3] = ca_ng;  wd.Wt[3] = wtq2;            wd.K[3] = F;   wd.N[3] = MID;
    wd.W[4] = ca_wkv; wd.G[4] = ca_ncg; wd.Wt[4] = wtkv2;           wd.K[4] = F;   wd.N[4] = 2 * MID;
    wd.W[5] = ca_wo;  wd.G[5] = nullptr;wd.Wt[5] = wto2;            wd.K[5] = MID; wd.N[5] = F;
    int cum = 0;
    for (int i = 0; i < 6; i++) {
        wd.start[i] = cum;
        cum += (wd.N[i] / 32) * (wd.K[i] / 32);
    }
    wd.start[6] = cum;
    wtrans_all_kernel<<<cum, dim3(32, 8)>>>(wd);

    BDesc bd;
    bd.b[0] = sa_nb;  bd.W[0] = sa_wq;  bd.N[0] = MID;
    bd.b[1] = sa_ncb; bd.W[1] = sa_wkv; bd.N[1] = 2 * MID;
    bd.b[2] = ca_nb;  bd.W[2] = ca_wq;  bd.N[2] = MID;
    bd.b[3] = ca_ncb; bd.W[3] = ca_wkv; bd.N[3] = 2 * MID;
    int bcum = 0;
    for (int i = 0; i < 4; i++) { bd.startblk[i] = bcum; bcum += bd.N[i] / 256; }
    bd.startblk[4] = bcum;
    bvec_part_kernel<<<dim3(bcum, 8), 256>>>(bd, bpart);

    // fused: rel-pos tables (512 blocks) + bvec reduce (bcum blocks)
    bias2_sum_kernel<<<512 + bcum, 256>>>(sa_rel, ca_rel, tbl, bpart, bvec, bcum);

    // ---------------- self pass (cross-KV work hoisted in) ----------------
    // LN(x) -> xh  AND  LN(ctx) -> ch in one launch
    lnw2_kernel<<<ROWS_X / 8 + ROWS_C / 8, 256>>>(x, xh, ROWS_X / 8, ctx, ch);

    // self QKV (768 tiles) + cross KV (128 tiles) in one launch
    {
        const int nx1 = 3 * MID / 128;          // 24
        const int nb1 = nx1 * (ROWS_X / 128);   // 768
        const int nx2 = 2 * MID / 128;          // 16
        const int nb2 = nx2 * (ROWS_C / 128);   // 128
        gemm_dual_kernel<<<nb1 + nb2, 256, GEMM_SMEM>>>(
            xh, wqkv, qkv, 3 * MID, nx1, nb1, bvec,
            ch, wtkv2, kvc, 2 * MID, nx2, bvec + 4 * MID, F);
    }

    attn_bf16<3 * MID, 3 * MID><<<dim3(NQ / 128, NHEAD, B), 256, ATTN_SMEM>>>(
        qkv, qkv + MID, ao, tbl, NQ, NQ, 0);
    gemm_bf16<false><<<dim3(F / 128, ROWS_X / 128), 256, GEMM_SMEM>>>(
        ao, wto, x1, ROWS_X, F, MID, sa_bo, x);

    // ---------------- cross pass ----------------
    lnw_kernel<<<ROWS_X / 8, 256>>>(x1, xh);
    gemm_bf16<true ><<<dim3(MID / 128, ROWS_X / 128), 256, GEMM_SMEM>>>(
        xh, wtq2, qc, ROWS_X, MID, F, bvec + 3 * MID, nullptr);
    attn_bf16<MID, 2 * MID><<<dim3(NQ / 128, NHEAD, B), 256, ATTN_SMEM>>>(
        qc, kvc, ao, tbl + NHEAD * 4096, NQ, NCTX, NCTX - NQ);
    gemm_bf16<false><<<dim3(F / 128, ROWS_X / 128), 256, GEMM_SMEM>>>(
        ao, wto2, out, ROWS_X, F, MID, ca_bo, x1);
}